// round 10
// baseline (speedup 1.0000x reference)
#include <cuda_runtime.h>
#include <cuda_fp16.h>
#include <math.h>
#include <stdint.h>

#define NN 50000
#define EE 850000

// -------- device scratch (no allocations allowed) --------
__device__ int g_deg[NN];
__device__ int g_cursor[NN];
__device__ int g_rowptr[NN + 1];
__device__ int g_srcs[EE];
__device__ __half g_xlh[(size_t)NN * 128];  // fp16 xl operand (both layers)
__device__ float g_xr[(size_t)NN * 128];    // fp32 xr operand (both layers)
__device__ float g_h[(size_t)NN * 128];     // layer-1 output (fp32)
__device__ float g_wt[4 * 8192];            // transposed weights

// ---------------- f32x2 packed math helpers ----------------
__device__ __forceinline__ unsigned long long pack2(float x) {
    unsigned long long r;
    asm("mov.b64 %0, {%1, %1};" : "=l"(r) : "f"(x));
    return r;
}
__device__ __forceinline__ unsigned long long fma2(unsigned long long a,
                                                   unsigned long long b,
                                                   unsigned long long c) {
    unsigned long long d;
    asm("fma.rn.f32x2 %0, %1, %2, %3;" : "=l"(d) : "l"(a), "l"(b), "l"(c));
    return d;
}
__device__ __forceinline__ float2 unpack2(unsigned long long v) {
    float2 r;
    asm("mov.b64 {%0, %1}, %2;" : "=f"(r.x), "=f"(r.y) : "l"(v));
    return r;
}

// ---------------- CSR build ----------------

// 8 edges per thread (2x int4)
__global__ void count_kernel(const int4* __restrict__ dst4, int e4,
                             const int* __restrict__ dst, int e) {
    int i0 = (blockIdx.x * blockDim.x + threadIdx.x) * 2;
    if (i0 < e4) {
        int4 d = dst4[i0];
        atomicAdd(&g_deg[d.x], 1);
        atomicAdd(&g_deg[d.y], 1);
        atomicAdd(&g_deg[d.z], 1);
        atomicAdd(&g_deg[d.w], 1);
    }
    if (i0 + 1 < e4) {
        int4 d = dst4[i0 + 1];
        atomicAdd(&g_deg[d.x], 1);
        atomicAdd(&g_deg[d.y], 1);
        atomicAdd(&g_deg[d.z], 1);
        atomicAdd(&g_deg[d.w], 1);
    }
    if (i0 == 0) {
        for (int k = 4 * e4; k < e; k++) atomicAdd(&g_deg[dst[k]], 1);
    }
}

// single-block exclusive scan; chunk=52 keeps ranges 4-aligned (int4 I/O)
__global__ void scan_kernel(int n) {
    __shared__ int sdata[1024];
    int t = threadIdx.x;
    const int ch = 52;
    int s0 = t * ch;
    int s1 = min(s0 + ch, n);
    int sum = 0;
    if (s0 < n) {
        int i = s0;
        for (; i + 4 <= s1; i += 4) {
            int4 d = *(const int4*)(g_deg + i);
            sum += d.x + d.y + d.z + d.w;
        }
        for (; i < s1; i++) sum += g_deg[i];
    }
    sdata[t] = sum;
    __syncthreads();
    for (int off = 1; off < 1024; off <<= 1) {
        int v = (t >= off) ? sdata[t - off] : 0;
        __syncthreads();
        sdata[t] += v;
        __syncthreads();
    }
    int run = sdata[t] - sum;
    if (s0 < n) {
        int i = s0;
        for (; i + 4 <= s1; i += 4) {
            int4 d = *(const int4*)(g_deg + i);
            int4 r;
            r.x = run;
            r.y = r.x + d.x;
            r.z = r.y + d.y;
            r.w = r.z + d.z;
            run = r.w + d.w;
            *(int4*)(g_rowptr + i) = r;
            *(int4*)(g_cursor + i) = r;
        }
        for (; i < s1; i++) {
            g_rowptr[i] = run;
            g_cursor[i] = run;
            run += g_deg[i];
        }
    }
    if (t == 1023) g_rowptr[n] = run;
}

__global__ void scatter_kernel(const int4* __restrict__ src4,
                               const int4* __restrict__ dst4, int e4,
                               const int* __restrict__ src,
                               const int* __restrict__ dst, int e) {
    int i0 = (blockIdx.x * blockDim.x + threadIdx.x) * 2;
    if (i0 < e4) {
        int4 s = src4[i0];
        int4 d = dst4[i0];
        g_srcs[atomicAdd(&g_cursor[d.x], 1)] = s.x;
        g_srcs[atomicAdd(&g_cursor[d.y], 1)] = s.y;
        g_srcs[atomicAdd(&g_cursor[d.z], 1)] = s.z;
        g_srcs[atomicAdd(&g_cursor[d.w], 1)] = s.w;
    }
    if (i0 + 1 < e4) {
        int4 s = src4[i0 + 1];
        int4 d = dst4[i0 + 1];
        g_srcs[atomicAdd(&g_cursor[d.x], 1)] = s.x;
        g_srcs[atomicAdd(&g_cursor[d.y], 1)] = s.y;
        g_srcs[atomicAdd(&g_cursor[d.z], 1)] = s.z;
        g_srcs[atomicAdd(&g_cursor[d.w], 1)] = s.w;
    }
    if (i0 == 0) {
        for (int k = 4 * e4; k < e; k++)
            g_srcs[atomicAdd(&g_cursor[dst[k]], 1)] = src[k];
    }
}

// ---------------- weight transpose (tiny, hidden under side chain) ----------
__global__ void wt_kernel(const float* __restrict__ Wl1,
                          const float* __restrict__ Wr1,
                          const float* __restrict__ Wl2,
                          const float* __restrict__ Wr2) {
    int idx = blockIdx.x * blockDim.x + threadIdx.x;   // 0 .. 32767
    int m = idx >> 13;
    int r = idx & 8191;
    const float* W = (m == 0) ? Wl1 : (m == 1) ? Wr1 : (m == 2) ? Wl2 : Wr2;
    int fin = (m < 2) ? 64 : 128;
    int fout = (m < 2) ? 128 : 64;
    int k = r / fout;
    int o = r - k * fout;
    g_wt[idx] = W[o * fin + k];   // Wt[k][o] = W[o][k]
}

// ---------------- smem dual linear ----------------
// branch 0: y = x@Wl^T+bl -> fp16 (xl operand); branch 1: fp32 (xr operand)
template <int FIN, int FOUT>
__global__ void __launch_bounds__(256)
linear2_kernel(const float* __restrict__ x,
               const float* __restrict__ Wt0,
               const float* __restrict__ b0,
               __half* __restrict__ y0h,
               const float* __restrict__ Wt1,
               const float* __restrict__ b1,
               float* __restrict__ y1f,
               int n) {
    constexpr int BN = 64;
    constexpr int KC = 32;
    constexpr int OT = FOUT / 4;
    constexpr int NT = 256 / OT;
    constexpr int NPT = BN / NT;
    constexpr int NP = NPT / 2;

    __shared__ float sW[KC * FOUT];
    __shared__ float sX[KC * BN];

    const float* Wt = blockIdx.y ? Wt1 : Wt0;
    const float* b = blockIdx.y ? b1 : b0;

    int tid = threadIdx.x;
    int ot = tid % OT;
    int nt = tid / OT;
    int nbase = blockIdx.x * BN;
    int n0 = nt * NPT;

    unsigned long long acc[NP][4];
#pragma unroll
    for (int q = 0; q < NP; q++)
#pragma unroll
        for (int j = 0; j < 4; j++) acc[q][j] = 0ull;

    for (int kc = 0; kc < FIN; kc += KC) {
        __syncthreads();
        {
            const float4* wsrc = (const float4*)(Wt + (size_t)kc * FOUT);
#pragma unroll
            for (int idx = tid; idx < KC * FOUT / 4; idx += 256)
                ((float4*)sW)[idx] = wsrc[idx];
        }
#pragma unroll
        for (int idx = tid; idx < (KC / 4) * BN; idx += 256) {
            int nn = idx % BN;
            int c4 = idx / BN;
            int node = nbase + nn;
            float4 xv = make_float4(0.f, 0.f, 0.f, 0.f);
            if (node < n) xv = *(const float4*)(x + (size_t)node * FIN + kc + 4 * c4);
            sX[(4 * c4 + 0) * BN + nn] = xv.x;
            sX[(4 * c4 + 1) * BN + nn] = xv.y;
            sX[(4 * c4 + 2) * BN + nn] = xv.z;
            sX[(4 * c4 + 3) * BN + nn] = xv.w;
        }
        __syncthreads();

#pragma unroll 8
        for (int k = 0; k < KC; k++) {
            float4 w = *(const float4*)(sW + k * FOUT + 4 * ot);
            unsigned long long w0 = pack2(w.x);
            unsigned long long w1 = pack2(w.y);
            unsigned long long w2 = pack2(w.z);
            unsigned long long w3 = pack2(w.w);
            const ulonglong2* xp = (const ulonglong2*)(sX + k * BN + n0);
#pragma unroll
            for (int q2 = 0; q2 < NP / 2; q2++) {
                ulonglong2 xv = xp[q2];
                acc[2 * q2][0] = fma2(xv.x, w0, acc[2 * q2][0]);
                acc[2 * q2][1] = fma2(xv.x, w1, acc[2 * q2][1]);
                acc[2 * q2][2] = fma2(xv.x, w2, acc[2 * q2][2]);
                acc[2 * q2][3] = fma2(xv.x, w3, acc[2 * q2][3]);
                acc[2 * q2 + 1][0] = fma2(xv.y, w0, acc[2 * q2 + 1][0]);
                acc[2 * q2 + 1][1] = fma2(xv.y, w1, acc[2 * q2 + 1][1]);
                acc[2 * q2 + 1][2] = fma2(xv.y, w2, acc[2 * q2 + 1][2]);
                acc[2 * q2 + 1][3] = fma2(xv.y, w3, acc[2 * q2 + 1][3]);
            }
        }
    }

    float4 bv = *(const float4*)(b + 4 * ot);
#pragma unroll
    for (int q = 0; q < NP; q++) {
        float2 o0 = unpack2(acc[q][0]);
        float2 o1 = unpack2(acc[q][1]);
        float2 o2 = unpack2(acc[q][2]);
        float2 o3 = unpack2(acc[q][3]);
        int na = nbase + n0 + 2 * q;
        float4 va = make_float4(o0.x + bv.x, o1.x + bv.y, o2.x + bv.z, o3.x + bv.w);
        float4 vb = make_float4(o0.y + bv.x, o1.y + bv.y, o2.y + bv.z, o3.y + bv.w);
        if (blockIdx.y == 0) {
            if (na < n) {
                __half2* yp = (__half2*)(y0h + (size_t)na * FOUT + 4 * ot);
                yp[0] = __floats2half2_rn(va.x, va.y);
                yp[1] = __floats2half2_rn(va.z, va.w);
            }
            if (na + 1 < n) {
                __half2* yp = (__half2*)(y0h + (size_t)(na + 1) * FOUT + 4 * ot);
                yp[0] = __floats2half2_rn(vb.x, vb.y);
                yp[1] = __floats2half2_rn(vb.z, vb.w);
            }
        } else {
            if (na < n)
                *(float4*)(y1f + (size_t)na * FOUT + 4 * ot) = va;
            if (na + 1 < n)
                *(float4*)(y1f + (size_t)(na + 1) * FOUT + 4 * ot) = vb;
        }
    }
}

// ---------------- fused GATv2 edge phase (fp16 gathers) ----------------
template <int U, int V, int G>
__device__ __forceinline__ void gat_block(const __half* __restrict__ xlh,
                                          const int* sidx, int cbase,
                                          const float (&xrv)[V],
                                          const float (&attv)[V],
                                          float (&acc)[V], float& z) {
    float a[U][V];
#pragma unroll
    for (int u = 0; u < U; u++) {
        const __half* p = xlh + (size_t)sidx[u] * (32 * V) + cbase;
        if constexpr (V == 4) {
            uint2 raw = *(const uint2*)p;
            float2 f0 = __half22float2(*reinterpret_cast<__half2*>(&raw.x));
            float2 f1 = __half22float2(*reinterpret_cast<__half2*>(&raw.y));
            a[u][0] = f0.x; a[u][1] = f0.y; a[u][2] = f1.x; a[u][3] = f1.y;
        } else {
            unsigned raw = *(const unsigned*)p;
            float2 f0 = __half22float2(*reinterpret_cast<__half2*>(&raw));
            a[u][0] = f0.x; a[u][1] = f0.y;
        }
    }
    float part[U];
#pragma unroll
    for (int u = 0; u < U; u++) {
        float pp = 0.f;
#pragma unroll
        for (int j = 0; j < V; j++) {
            float s = a[u][j] + xrv[j];
            s = (s > 0.f) ? s : 0.2f * s;
            pp += s * attv[j];
        }
        part[u] = pp;
    }
#pragma unroll
    for (int off = G / 2; off > 0; off >>= 1) {
#pragma unroll
        for (int u = 0; u < U; u++)
            part[u] += __shfl_xor_sync(0xffffffffu, part[u], off);
    }
    float p[U];
#pragma unroll
    for (int u = 0; u < U; u++) p[u] = __expf(part[u]);
#pragma unroll
    for (int u = 0; u < U; u++) z += p[u];
#pragma unroll
    for (int j = 0; j < V; j++) {
        float s = 0.f;
#pragma unroll
        for (int u = 0; u < U; u++) s += p[u] * a[u][j];
        acc[j] += s;
    }
}

template <int H, int C, bool ELU>
__global__ void gat_kernel(const __half* __restrict__ xlh,
                           const float* __restrict__ xr,
                           const float* __restrict__ att,
                           const float* __restrict__ bias,
                           float* __restrict__ out, int n) {
    constexpr int F = H * C;
    constexpr int V = F / 32;
    constexpr int G = 32 / H;

    int wid = (blockIdx.x * blockDim.x + threadIdx.x) >> 5;
    int lane = threadIdx.x & 31;
    if (wid >= n) return;
    int i = wid;
    int cbase = lane * V;

    float xrv[V], attv[V], acc[V];
    {
        const float* xp = xr + (size_t)i * F + cbase;
        if constexpr (V == 4) {
            float4 t = *(const float4*)xp;
            xrv[0] = t.x; xrv[1] = t.y; xrv[2] = t.z; xrv[3] = t.w;
        } else {
            float2 t = *(const float2*)xp;
            xrv[0] = t.x; xrv[1] = t.y;
        }
    }
#pragma unroll
    for (int j = 0; j < V; j++) { attv[j] = att[cbase + j]; acc[j] = 0.f; }

    float z = 0.f;
    int beg = g_rowptr[i], end = g_rowptr[i + 1];
    int k = beg;

    // 8-edge blocks with index double-buffering: indices for block b+1 are
    // issued before block b's compute, removing one L2 latency per round.
    int nfull = (end - beg) >> 3;
    if (nfull > 0) {
        int s[8], snext[8];
#pragma unroll
        for (int u = 0; u < 8; u++) s[u] = __ldg(g_srcs + k + u);
        for (int bidx = 0; bidx < nfull; bidx++) {
            if (bidx + 1 < nfull) {
#pragma unroll
                for (int u = 0; u < 8; u++)
                    snext[u] = __ldg(g_srcs + k + 8 + u);
            }
            gat_block<8, V, G>(xlh, s, cbase, xrv, attv, acc, z);
            k += 8;
#pragma unroll
            for (int u = 0; u < 8; u++) s[u] = snext[u];
        }
    }
    if (k + 4 <= end) {
        int s[4];
#pragma unroll
        for (int u = 0; u < 4; u++) s[u] = __ldg(g_srcs + k + u);
        gat_block<4, V, G>(xlh, s, cbase, xrv, attv, acc, z);
        k += 4;
    }
    for (; k < end; k++) {
        int s[1] = {__ldg(g_srcs + k)};
        gat_block<1, V, G>(xlh, s, cbase, xrv, attv, acc, z);
    }

    float inv = 1.f / (z + 1e-16f);
    float ov[V];
#pragma unroll
    for (int j = 0; j < V; j++) {
        float v = acc[j] * inv + bias[cbase + j];
        if constexpr (ELU) v = (v > 0.f) ? v : (__expf(v) - 1.f);
        ov[j] = v;
    }
    float* op = out + (size_t)i * F + cbase;
    if constexpr (V == 4)
        *(float4*)op = make_float4(ov[0], ov[1], ov[2], ov[3]);
    else
        *(float2*)op = make_float2(ov[0], ov[1]);
}

// ---------------- launch ----------------

extern "C" void kernel_launch(void* const* d_in, const int* in_sizes, int n_in,
                              void* d_out, int out_size) {
    const float* x    = (const float*)d_in[0];
    const int*   ei   = (const int*)d_in[1];
    const float* Wl1  = (const float*)d_in[2];
    const float* bl1  = (const float*)d_in[3];
    const float* Wr1  = (const float*)d_in[4];
    const float* br1  = (const float*)d_in[5];
    const float* att1 = (const float*)d_in[6];
    const float* bias1= (const float*)d_in[7];
    const float* Wl2  = (const float*)d_in[8];
    const float* bl2  = (const float*)d_in[9];
    const float* Wr2  = (const float*)d_in[10];
    const float* br2  = (const float*)d_in[11];
    const float* att2 = (const float*)d_in[12];
    const float* bias2= (const float*)d_in[13];
    float* out = (float*)d_out;

    int n = in_sizes[0] / 64;   // 50000
    int e = in_sizes[1] / 2;    // 850000
    const int* src = ei;
    const int* dst = ei + e;
    int e4 = 0;
    if ((((unsigned long long)(size_t)src) & 15ull) == 0 &&
        (((unsigned long long)(size_t)dst) & 15ull) == 0) e4 = e / 4;

    __half* xlhp;
    float *xrp, *hp, *wtp;
    int* degp;
    cudaGetSymbolAddress((void**)&xlhp, g_xlh);
    cudaGetSymbolAddress((void**)&xrp, g_xr);
    cudaGetSymbolAddress((void**)&hp,  g_h);
    cudaGetSymbolAddress((void**)&wtp, g_wt);
    cudaGetSymbolAddress((void**)&degp, g_deg);

    static cudaStream_t s_side = nullptr;
    static cudaEvent_t ev_fork = nullptr, ev_join = nullptr;
    if (s_side == nullptr) {
        cudaStreamCreateWithFlags(&s_side, cudaStreamNonBlocking);
        cudaEventCreateWithFlags(&ev_fork, cudaEventDisableTiming);
        cudaEventCreateWithFlags(&ev_join, cudaEventDisableTiming);
    }

    // fork: CSR build on side stream, concurrent with wt + linear1 on main
    cudaEventRecord(ev_fork, 0);
    cudaStreamWaitEvent(s_side, ev_fork, 0);

    int ethreads = (e4 + 1) / 2;   // 8 edges per thread
    cudaMemsetAsync(degp, 0, n * sizeof(int), s_side);
    count_kernel<<<(max(ethreads, 1) + 255) / 256, 256, 0, s_side>>>(
        (const int4*)dst, e4, dst, e);
    scan_kernel<<<1, 1024, 0, s_side>>>(n);
    scatter_kernel<<<(max(ethreads, 1) + 255) / 256, 256, 0, s_side>>>(
        (const int4*)src, (const int4*)dst, e4, src, dst, e);
    cudaEventRecord(ev_join, s_side);

    // main stream: weight transpose + layer-1 linears
    wt_kernel<<<128, 256>>>(Wl1, Wr1, Wl2, Wr2);
    dim3 lgrid((n + 63) / 64, 2);
    linear2_kernel<64, 128><<<lgrid, 256>>>(
        x, wtp, bl1, xlhp, wtp + 8192, br1, xrp, n);

    // join: gat1 needs CSR + linear1
    cudaStreamWaitEvent(0, ev_join, 0);

    gat_kernel<4, 32, true><<<(n + 7) / 8, 256>>>(xlhp, xrp, att1, bias1, hp, n);

    linear2_kernel<128, 64><<<lgrid, 256>>>(
        hp, wtp + 16384, bl2, xlhp, wtp + 24576, br2, xrp, n);

    gat_kernel<1, 64, false><<<(n + 7) / 8, 256>>>(xlhp, xrp, att2, bias2, out, n);
}

// round 11
// speedup vs baseline: 1.1274x; 1.1274x over previous
#include <cuda_runtime.h>
#include <cuda_fp16.h>
#include <math.h>
#include <stdint.h>

#define NN 50000
#define EE 850000

// -------- device scratch (no allocations allowed) --------
// g_deg is zero at module load and re-zeroed by scan_kernel every call,
// so no memset is needed in the launch sequence.
__device__ int g_deg[NN];
__device__ int g_cursor[NN];
__device__ int g_rowptr[NN + 1];
__device__ int g_srcs[EE];
__device__ __half g_xlh[(size_t)NN * 128];  // fp16 xl operand (both layers)
__device__ float g_xr[(size_t)NN * 128];    // fp32 xr operand (both layers)
__device__ float g_h[(size_t)NN * 128];     // layer-1 output (fp32)
__device__ float g_wt[4 * 8192];            // transposed weights

// ---------------- f32x2 packed math helpers ----------------
__device__ __forceinline__ unsigned long long pack2(float x) {
    unsigned long long r;
    asm("mov.b64 %0, {%1, %1};" : "=l"(r) : "f"(x));
    return r;
}
__device__ __forceinline__ unsigned long long fma2(unsigned long long a,
                                                   unsigned long long b,
                                                   unsigned long long c) {
    unsigned long long d;
    asm("fma.rn.f32x2 %0, %1, %2, %3;" : "=l"(d) : "l"(a), "l"(b), "l"(c));
    return d;
}
__device__ __forceinline__ float2 unpack2(unsigned long long v) {
    float2 r;
    asm("mov.b64 {%0, %1}, %2;" : "=f"(r.x), "=f"(r.y) : "l"(v));
    return r;
}

// ---------------- CSR build ----------------

// 8 edges per thread (2x int4)
__global__ void count_kernel(const int4* __restrict__ dst4, int e4,
                             const int* __restrict__ dst, int e) {
    int i0 = (blockIdx.x * blockDim.x + threadIdx.x) * 2;
    if (i0 < e4) {
        int4 d = dst4[i0];
        atomicAdd(&g_deg[d.x], 1);
        atomicAdd(&g_deg[d.y], 1);
        atomicAdd(&g_deg[d.z], 1);
        atomicAdd(&g_deg[d.w], 1);
    }
    if (i0 + 1 < e4) {
        int4 d = dst4[i0 + 1];
        atomicAdd(&g_deg[d.x], 1);
        atomicAdd(&g_deg[d.y], 1);
        atomicAdd(&g_deg[d.z], 1);
        atomicAdd(&g_deg[d.w], 1);
    }
    if (i0 == 0) {
        for (int k = 4 * e4; k < e; k++) atomicAdd(&g_deg[dst[k]], 1);
    }
}

// single-block exclusive scan; chunk=52 keeps ranges 4-aligned (int4 I/O).
// Re-zeros g_deg during the prefix pass so the next call needs no memset.
__global__ void scan_kernel(int n) {
    __shared__ int sdata[1024];
    int t = threadIdx.x;
    const int ch = 52;
    int s0 = t * ch;
    int s1 = min(s0 + ch, n);
    int sum = 0;
    if (s0 < n) {
        int i = s0;
        for (; i + 4 <= s1; i += 4) {
            int4 d = *(const int4*)(g_deg + i);
            sum += d.x + d.y + d.z + d.w;
        }
        for (; i < s1; i++) sum += g_deg[i];
    }
    sdata[t] = sum;
    __syncthreads();
    for (int off = 1; off < 1024; off <<= 1) {
        int v = (t >= off) ? sdata[t - off] : 0;
        __syncthreads();
        sdata[t] += v;
        __syncthreads();
    }
    int run = sdata[t] - sum;
    if (s0 < n) {
        const int4 zero4 = make_int4(0, 0, 0, 0);
        int i = s0;
        for (; i + 4 <= s1; i += 4) {
            int4 d = *(const int4*)(g_deg + i);
            int4 r;
            r.x = run;
            r.y = r.x + d.x;
            r.z = r.y + d.y;
            r.w = r.z + d.z;
            run = r.w + d.w;
            *(int4*)(g_rowptr + i) = r;
            *(int4*)(g_cursor + i) = r;
            *(int4*)(g_deg + i) = zero4;   // ready for next call
        }
        for (; i < s1; i++) {
            g_rowptr[i] = run;
            g_cursor[i] = run;
            run += g_deg[i];
            g_deg[i] = 0;
        }
    }
    if (t == 1023) g_rowptr[n] = run;
}

__global__ void scatter_kernel(const int4* __restrict__ src4,
                               const int4* __restrict__ dst4, int e4,
                               const int* __restrict__ src,
                               const int* __restrict__ dst, int e) {
    int i0 = (blockIdx.x * blockDim.x + threadIdx.x) * 2;
    if (i0 < e4) {
        int4 s = src4[i0];
        int4 d = dst4[i0];
        g_srcs[atomicAdd(&g_cursor[d.x], 1)] = s.x;
        g_srcs[atomicAdd(&g_cursor[d.y], 1)] = s.y;
        g_srcs[atomicAdd(&g_cursor[d.z], 1)] = s.z;
        g_srcs[atomicAdd(&g_cursor[d.w], 1)] = s.w;
    }
    if (i0 + 1 < e4) {
        int4 s = src4[i0 + 1];
        int4 d = dst4[i0 + 1];
        g_srcs[atomicAdd(&g_cursor[d.x], 1)] = s.x;
        g_srcs[atomicAdd(&g_cursor[d.y], 1)] = s.y;
        g_srcs[atomicAdd(&g_cursor[d.z], 1)] = s.z;
        g_srcs[atomicAdd(&g_cursor[d.w], 1)] = s.w;
    }
    if (i0 == 0) {
        for (int k = 4 * e4; k < e; k++)
            g_srcs[atomicAdd(&g_cursor[dst[k]], 1)] = src[k];
    }
}

// ---------------- weight transpose (tiny) ----------------
__global__ void wt_kernel(const float* __restrict__ Wl1,
                          const float* __restrict__ Wr1,
                          const float* __restrict__ Wl2,
                          const float* __restrict__ Wr2) {
    int idx = blockIdx.x * blockDim.x + threadIdx.x;   // 0 .. 32767
    int m = idx >> 13;
    int r = idx & 8191;
    const float* W = (m == 0) ? Wl1 : (m == 1) ? Wr1 : (m == 2) ? Wl2 : Wr2;
    int fin = (m < 2) ? 64 : 128;
    int fout = (m < 2) ? 128 : 64;
    int k = r / fout;
    int o = r - k * fout;
    g_wt[idx] = W[o * fin + k];   // Wt[k][o] = W[o][k]
}

// ---------------- smem dual linear ----------------
// branch 0: y = x@Wl^T+bl -> fp16 (xl operand); branch 1: fp32 (xr operand)
template <int FIN, int FOUT>
__global__ void __launch_bounds__(256)
linear2_kernel(const float* __restrict__ x,
               const float* __restrict__ Wt0,
               const float* __restrict__ b0,
               __half* __restrict__ y0h,
               const float* __restrict__ Wt1,
               const float* __restrict__ b1,
               float* __restrict__ y1f,
               int n) {
    constexpr int BN = 64;
    constexpr int KC = 32;
    constexpr int OT = FOUT / 4;
    constexpr int NT = 256 / OT;
    constexpr int NPT = BN / NT;
    constexpr int NP = NPT / 2;

    __shared__ float sW[KC * FOUT];
    __shared__ float sX[KC * BN];

    const float* Wt = blockIdx.y ? Wt1 : Wt0;
    const float* b = blockIdx.y ? b1 : b0;

    int tid = threadIdx.x;
    int ot = tid % OT;
    int nt = tid / OT;
    int nbase = blockIdx.x * BN;
    int n0 = nt * NPT;

    unsigned long long acc[NP][4];
#pragma unroll
    for (int q = 0; q < NP; q++)
#pragma unroll
        for (int j = 0; j < 4; j++) acc[q][j] = 0ull;

    for (int kc = 0; kc < FIN; kc += KC) {
        __syncthreads();
        {
            const float4* wsrc = (const float4*)(Wt + (size_t)kc * FOUT);
#pragma unroll
            for (int idx = tid; idx < KC * FOUT / 4; idx += 256)
                ((float4*)sW)[idx] = wsrc[idx];
        }
#pragma unroll
        for (int idx = tid; idx < (KC / 4) * BN; idx += 256) {
            int nn = idx % BN;
            int c4 = idx / BN;
            int node = nbase + nn;
            float4 xv = make_float4(0.f, 0.f, 0.f, 0.f);
            if (node < n) xv = *(const float4*)(x + (size_t)node * FIN + kc + 4 * c4);
            sX[(4 * c4 + 0) * BN + nn] = xv.x;
            sX[(4 * c4 + 1) * BN + nn] = xv.y;
            sX[(4 * c4 + 2) * BN + nn] = xv.z;
            sX[(4 * c4 + 3) * BN + nn] = xv.w;
        }
        __syncthreads();

#pragma unroll 8
        for (int k = 0; k < KC; k++) {
            float4 w = *(const float4*)(sW + k * FOUT + 4 * ot);
            unsigned long long w0 = pack2(w.x);
            unsigned long long w1 = pack2(w.y);
            unsigned long long w2 = pack2(w.z);
            unsigned long long w3 = pack2(w.w);
            const ulonglong2* xp = (const ulonglong2*)(sX + k * BN + n0);
#pragma unroll
            for (int q2 = 0; q2 < NP / 2; q2++) {
                ulonglong2 xv = xp[q2];
                acc[2 * q2][0] = fma2(xv.x, w0, acc[2 * q2][0]);
                acc[2 * q2][1] = fma2(xv.x, w1, acc[2 * q2][1]);
                acc[2 * q2][2] = fma2(xv.x, w2, acc[2 * q2][2]);
                acc[2 * q2][3] = fma2(xv.x, w3, acc[2 * q2][3]);
                acc[2 * q2 + 1][0] = fma2(xv.y, w0, acc[2 * q2 + 1][0]);
                acc[2 * q2 + 1][1] = fma2(xv.y, w1, acc[2 * q2 + 1][1]);
                acc[2 * q2 + 1][2] = fma2(xv.y, w2, acc[2 * q2 + 1][2]);
                acc[2 * q2 + 1][3] = fma2(xv.y, w3, acc[2 * q2 + 1][3]);
            }
        }
    }

    float4 bv = *(const float4*)(b + 4 * ot);
#pragma unroll
    for (int q = 0; q < NP; q++) {
        float2 o0 = unpack2(acc[q][0]);
        float2 o1 = unpack2(acc[q][1]);
        float2 o2 = unpack2(acc[q][2]);
        float2 o3 = unpack2(acc[q][3]);
        int na = nbase + n0 + 2 * q;
        float4 va = make_float4(o0.x + bv.x, o1.x + bv.y, o2.x + bv.z, o3.x + bv.w);
        float4 vb = make_float4(o0.y + bv.x, o1.y + bv.y, o2.y + bv.z, o3.y + bv.w);
        if (blockIdx.y == 0) {
            if (na < n) {
                __half2* yp = (__half2*)(y0h + (size_t)na * FOUT + 4 * ot);
                yp[0] = __floats2half2_rn(va.x, va.y);
                yp[1] = __floats2half2_rn(va.z, va.w);
            }
            if (na + 1 < n) {
                __half2* yp = (__half2*)(y0h + (size_t)(na + 1) * FOUT + 4 * ot);
                yp[0] = __floats2half2_rn(vb.x, vb.y);
                yp[1] = __floats2half2_rn(vb.z, vb.w);
            }
        } else {
            if (na < n)
                *(float4*)(y1f + (size_t)na * FOUT + 4 * ot) = va;
            if (na + 1 < n)
                *(float4*)(y1f + (size_t)(na + 1) * FOUT + 4 * ot) = vb;
        }
    }
}

// ---------------- fused GATv2 edge phase (fp16 gathers) ----------------
template <int U, int V, int G>
__device__ __forceinline__ void gat_block(const __half* __restrict__ xlh,
                                          const int* sidx, int cbase,
                                          const float (&xrv)[V],
                                          const float (&attv)[V],
                                          float (&acc)[V], float& z) {
    float a[U][V];
#pragma unroll
    for (int u = 0; u < U; u++) {
        const __half* p = xlh + (size_t)sidx[u] * (32 * V) + cbase;
        if constexpr (V == 4) {
            uint2 raw = *(const uint2*)p;
            float2 f0 = __half22float2(*reinterpret_cast<__half2*>(&raw.x));
            float2 f1 = __half22float2(*reinterpret_cast<__half2*>(&raw.y));
            a[u][0] = f0.x; a[u][1] = f0.y; a[u][2] = f1.x; a[u][3] = f1.y;
        } else {
            unsigned raw = *(const unsigned*)p;
            float2 f0 = __half22float2(*reinterpret_cast<__half2*>(&raw));
            a[u][0] = f0.x; a[u][1] = f0.y;
        }
    }
    float part[U];
#pragma unroll
    for (int u = 0; u < U; u++) {
        float pp = 0.f;
#pragma unroll
        for (int j = 0; j < V; j++) {
            float s = a[u][j] + xrv[j];
            s = (s > 0.f) ? s : 0.2f * s;
            pp += s * attv[j];
        }
        part[u] = pp;
    }
#pragma unroll
    for (int off = G / 2; off > 0; off >>= 1) {
#pragma unroll
        for (int u = 0; u < U; u++)
            part[u] += __shfl_xor_sync(0xffffffffu, part[u], off);
    }
    float p[U];
#pragma unroll
    for (int u = 0; u < U; u++) p[u] = __expf(part[u]);
#pragma unroll
    for (int u = 0; u < U; u++) z += p[u];
#pragma unroll
    for (int j = 0; j < V; j++) {
        float s = 0.f;
#pragma unroll
        for (int u = 0; u < U; u++) s += p[u] * a[u][j];
        acc[j] += s;
    }
}

template <int H, int C, bool ELU>
__global__ void gat_kernel(const __half* __restrict__ xlh,
                           const float* __restrict__ xr,
                           const float* __restrict__ att,
                           const float* __restrict__ bias,
                           float* __restrict__ out, int n) {
    constexpr int F = H * C;
    constexpr int V = F / 32;
    constexpr int G = 32 / H;

    int wid = (blockIdx.x * blockDim.x + threadIdx.x) >> 5;
    int lane = threadIdx.x & 31;
    if (wid >= n) return;
    int i = wid;
    int cbase = lane * V;

    float xrv[V], attv[V], acc[V];
    {
        const float* xp = xr + (size_t)i * F + cbase;
        if constexpr (V == 4) {
            float4 t = *(const float4*)xp;
            xrv[0] = t.x; xrv[1] = t.y; xrv[2] = t.z; xrv[3] = t.w;
        } else {
            float2 t = *(const float2*)xp;
            xrv[0] = t.x; xrv[1] = t.y;
        }
    }
#pragma unroll
    for (int j = 0; j < V; j++) { attv[j] = att[cbase + j]; acc[j] = 0.f; }

    float z = 0.f;
    int beg = g_rowptr[i], end = g_rowptr[i + 1];
    int k = beg;

    for (; k + 8 <= end; k += 8) {
        int s[8];
#pragma unroll
        for (int u = 0; u < 8; u++) s[u] = __ldg(g_srcs + k + u);
        gat_block<8, V, G>(xlh, s, cbase, xrv, attv, acc, z);
    }
    if (k + 4 <= end) {
        int s[4];
#pragma unroll
        for (int u = 0; u < 4; u++) s[u] = __ldg(g_srcs + k + u);
        gat_block<4, V, G>(xlh, s, cbase, xrv, attv, acc, z);
        k += 4;
    }
    for (; k < end; k++) {
        int s[1] = {__ldg(g_srcs + k)};
        gat_block<1, V, G>(xlh, s, cbase, xrv, attv, acc, z);
    }

    float inv = 1.f / (z + 1e-16f);
    float ov[V];
#pragma unroll
    for (int j = 0; j < V; j++) {
        float v = acc[j] * inv + bias[cbase + j];
        if constexpr (ELU) v = (v > 0.f) ? v : (__expf(v) - 1.f);
        ov[j] = v;
    }
    float* op = out + (size_t)i * F + cbase;
    if constexpr (V == 4)
        *(float4*)op = make_float4(ov[0], ov[1], ov[2], ov[3]);
    else
        *(float2*)op = make_float2(ov[0], ov[1]);
}

// ---------------- launch ----------------

extern "C" void kernel_launch(void* const* d_in, const int* in_sizes, int n_in,
                              void* d_out, int out_size) {
    const float* x    = (const float*)d_in[0];
    const int*   ei   = (const int*)d_in[1];
    const float* Wl1  = (const float*)d_in[2];
    const float* bl1  = (const float*)d_in[3];
    const float* Wr1  = (const float*)d_in[4];
    const float* br1  = (const float*)d_in[5];
    const float* att1 = (const float*)d_in[6];
    const float* bias1= (const float*)d_in[7];
    const float* Wl2  = (const float*)d_in[8];
    const float* bl2  = (const float*)d_in[9];
    const float* Wr2  = (const float*)d_in[10];
    const float* br2  = (const float*)d_in[11];
    const float* att2 = (const float*)d_in[12];
    const float* bias2= (const float*)d_in[13];
    float* out = (float*)d_out;

    int n = in_sizes[0] / 64;   // 50000
    int e = in_sizes[1] / 2;    // 850000
    const int* src = ei;
    const int* dst = ei + e;
    int e4 = 0;
    if ((((unsigned long long)(size_t)src) & 15ull) == 0 &&
        (((unsigned long long)(size_t)dst) & 15ull) == 0) e4 = e / 4;

    __half* xlhp;
    float *xrp, *hp, *wtp;
    cudaGetSymbolAddress((void**)&xlhp, g_xlh);
    cudaGetSymbolAddress((void**)&xrp, g_xr);
    cudaGetSymbolAddress((void**)&hp,  g_h);
    cudaGetSymbolAddress((void**)&wtp, g_wt);

    static cudaStream_t s_side = nullptr;
    static cudaEvent_t ev_fork = nullptr, ev_join = nullptr;
    if (s_side == nullptr) {
        cudaStreamCreateWithFlags(&s_side, cudaStreamNonBlocking);
        cudaEventCreateWithFlags(&ev_fork, cudaEventDisableTiming);
        cudaEventCreateWithFlags(&ev_join, cudaEventDisableTiming);
    }

    // fork: CSR build on side stream, concurrent with wt + linear1 on main.
    // (g_deg arrives zeroed: zero-init at load, re-zeroed by scan_kernel.)
    cudaEventRecord(ev_fork, 0);
    cudaStreamWaitEvent(s_side, ev_fork, 0);

    int ethreads = (e4 + 1) / 2;   // 8 edges per thread
    count_kernel<<<(max(ethreads, 1) + 255) / 256, 256, 0, s_side>>>(
        (const int4*)dst, e4, dst, e);
    scan_kernel<<<1, 1024, 0, s_side>>>(n);
    scatter_kernel<<<(max(ethreads, 1) + 255) / 256, 256, 0, s_side>>>(
        (const int4*)src, (const int4*)dst, e4, src, dst, e);
    cudaEventRecord(ev_join, s_side);

    // main stream: weight transpose + layer-1 linears
    wt_kernel<<<128, 256>>>(Wl1, Wr1, Wl2, Wr2);
    dim3 lgrid((n + 63) / 64, 2);
    linear2_kernel<64, 128><<<lgrid, 256>>>(
        x, wtp, bl1, xlhp, wtp + 8192, br1, xrp, n);

    // join: gat1 needs CSR + linear1
    cudaStreamWaitEvent(0, ev_join, 0);

    gat_kernel<4, 32, true><<<(n + 7) / 8, 256>>>(xlhp, xrp, att1, bias1, hp, n);

    linear2_kernel<128, 64><<<lgrid, 256>>>(
        hp, wtp + 16384, bl2, xlhp, wtp + 24576, br2, xrp, n);

    gat_kernel<1, 64, false><<<(n + 7) / 8, 256>>>(xlhp, xrp, att2, bias2, out, n);
}

// round 12
// speedup vs baseline: 1.1707x; 1.0383x over previous
#include <cuda_runtime.h>
#include <cuda_fp16.h>
#include <math.h>
#include <stdint.h>

#define NN 50000
#define EE 850000

// -------- device scratch (no allocations allowed) --------
// g_deg is zero at module load and re-zeroed by scan_kernel every call.
__device__ int g_deg[NN];
__device__ int g_cursor[NN];
__device__ int g_rowptr[NN + 1];
__device__ int g_srcs[EE];
__device__ __half g_xlh[(size_t)NN * 128];  // fp16 xl operand (both layers)
__device__ float g_xr[(size_t)NN * 128];    // fp32 xr operand (both layers)
__device__ __half g_hh[(size_t)NN * 128];   // layer-1 output (fp16)
__device__ float g_wt[4 * 8192];            // transposed weights

// ---------------- f32x2 packed math helpers ----------------
__device__ __forceinline__ unsigned long long pack2(float x) {
    unsigned long long r;
    asm("mov.b64 %0, {%1, %1};" : "=l"(r) : "f"(x));
    return r;
}
__device__ __forceinline__ unsigned long long fma2(unsigned long long a,
                                                   unsigned long long b,
                                                   unsigned long long c) {
    unsigned long long d;
    asm("fma.rn.f32x2 %0, %1, %2, %3;" : "=l"(d) : "l"(a), "l"(b), "l"(c));
    return d;
}
__device__ __forceinline__ float2 unpack2(unsigned long long v) {
    float2 r;
    asm("mov.b64 {%0, %1}, %2;" : "=f"(r.x), "=f"(r.y) : "l"(v));
    return r;
}

// ---------------- CSR build (R8 config: 4 edges/thread) ----------------

__global__ void count_kernel(const int4* __restrict__ dst4, int e4,
                             const int* __restrict__ dst, int e) {
    int i = blockIdx.x * blockDim.x + threadIdx.x;
    if (i < e4) {
        int4 d = dst4[i];
        atomicAdd(&g_deg[d.x], 1);
        atomicAdd(&g_deg[d.y], 1);
        atomicAdd(&g_deg[d.z], 1);
        atomicAdd(&g_deg[d.w], 1);
    }
    if (i == 0) {
        for (int k = 4 * e4; k < e; k++) atomicAdd(&g_deg[dst[k]], 1);
    }
}

// single-block exclusive scan; chunk=52 keeps ranges 4-aligned (int4 I/O).
// Re-zeros g_deg during the prefix pass so no memset launch is needed.
__global__ void scan_kernel(int n) {
    __shared__ int sdata[1024];
    int t = threadIdx.x;
    const int ch = 52;
    int s0 = t * ch;
    int s1 = min(s0 + ch, n);
    int sum = 0;
    if (s0 < n) {
        int i = s0;
        for (; i + 4 <= s1; i += 4) {
            int4 d = *(const int4*)(g_deg + i);
            sum += d.x + d.y + d.z + d.w;
        }
        for (; i < s1; i++) sum += g_deg[i];
    }
    sdata[t] = sum;
    __syncthreads();
    for (int off = 1; off < 1024; off <<= 1) {
        int v = (t >= off) ? sdata[t - off] : 0;
        __syncthreads();
        sdata[t] += v;
        __syncthreads();
    }
    int run = sdata[t] - sum;
    if (s0 < n) {
        const int4 zero4 = make_int4(0, 0, 0, 0);
        int i = s0;
        for (; i + 4 <= s1; i += 4) {
            int4 d = *(const int4*)(g_deg + i);
            int4 r;
            r.x = run;
            r.y = r.x + d.x;
            r.z = r.y + d.y;
            r.w = r.z + d.z;
            run = r.w + d.w;
            *(int4*)(g_rowptr + i) = r;
            *(int4*)(g_cursor + i) = r;
            *(int4*)(g_deg + i) = zero4;
        }
        for (; i < s1; i++) {
            g_rowptr[i] = run;
            g_cursor[i] = run;
            run += g_deg[i];
            g_deg[i] = 0;
        }
    }
    if (t == 1023) g_rowptr[n] = run;
}

__global__ void scatter_kernel(const int4* __restrict__ src4,
                               const int4* __restrict__ dst4, int e4,
                               const int* __restrict__ src,
                               const int* __restrict__ dst, int e) {
    int i = blockIdx.x * blockDim.x + threadIdx.x;
    if (i < e4) {
        int4 s = src4[i];
        int4 d = dst4[i];
        g_srcs[atomicAdd(&g_cursor[d.x], 1)] = s.x;
        g_srcs[atomicAdd(&g_cursor[d.y], 1)] = s.y;
        g_srcs[atomicAdd(&g_cursor[d.z], 1)] = s.z;
        g_srcs[atomicAdd(&g_cursor[d.w], 1)] = s.w;
    }
    if (i == 0) {
        for (int k = 4 * e4; k < e; k++)
            g_srcs[atomicAdd(&g_cursor[dst[k]], 1)] = src[k];
    }
}

// ---------------- weight transpose (tiny) ----------------
__global__ void wt_kernel(const float* __restrict__ Wl1,
                          const float* __restrict__ Wr1,
                          const float* __restrict__ Wl2,
                          const float* __restrict__ Wr2) {
    int idx = blockIdx.x * blockDim.x + threadIdx.x;   // 0 .. 32767
    int m = idx >> 13;
    int r = idx & 8191;
    const float* W = (m == 0) ? Wl1 : (m == 1) ? Wr1 : (m == 2) ? Wl2 : Wr2;
    int fin = (m < 2) ? 64 : 128;
    int fout = (m < 2) ? 128 : 64;
    int k = r / fout;
    int o = r - k * fout;
    g_wt[idx] = W[o * fin + k];   // Wt[k][o] = W[o][k]
}

// ---------------- smem dual linear ----------------
// INH: input x is fp16 (converted during sX staging).
// branch 0: y = x@Wl^T+bl -> fp16 (xl operand); branch 1: fp32 (xr operand)
template <int FIN, int FOUT, bool INH>
__global__ void __launch_bounds__(256)
linear2_kernel(const void* __restrict__ xin,
               const float* __restrict__ Wt0,
               const float* __restrict__ b0,
               __half* __restrict__ y0h,
               const float* __restrict__ Wt1,
               const float* __restrict__ b1,
               float* __restrict__ y1f,
               int n) {
    constexpr int BN = 64;
    constexpr int KC = 32;
    constexpr int OT = FOUT / 4;
    constexpr int NT = 256 / OT;
    constexpr int NPT = BN / NT;
    constexpr int NP = NPT / 2;

    __shared__ float sW[KC * FOUT];
    __shared__ float sX[KC * BN];

    const float* Wt = blockIdx.y ? Wt1 : Wt0;
    const float* b = blockIdx.y ? b1 : b0;

    int tid = threadIdx.x;
    int ot = tid % OT;
    int nt = tid / OT;
    int nbase = blockIdx.x * BN;
    int n0 = nt * NPT;

    unsigned long long acc[NP][4];
#pragma unroll
    for (int q = 0; q < NP; q++)
#pragma unroll
        for (int j = 0; j < 4; j++) acc[q][j] = 0ull;

    for (int kc = 0; kc < FIN; kc += KC) {
        __syncthreads();
        {
            const float4* wsrc = (const float4*)(Wt + (size_t)kc * FOUT);
#pragma unroll
            for (int idx = tid; idx < KC * FOUT / 4; idx += 256)
                ((float4*)sW)[idx] = wsrc[idx];
        }
#pragma unroll
        for (int idx = tid; idx < (KC / 4) * BN; idx += 256) {
            int nn = idx % BN;
            int c4 = idx / BN;
            int node = nbase + nn;
            float4 xv = make_float4(0.f, 0.f, 0.f, 0.f);
            if (node < n) {
                if constexpr (INH) {
                    uint2 raw = *(const uint2*)((const __half*)xin +
                                                (size_t)node * FIN + kc + 4 * c4);
                    float2 f0 = __half22float2(*reinterpret_cast<__half2*>(&raw.x));
                    float2 f1 = __half22float2(*reinterpret_cast<__half2*>(&raw.y));
                    xv = make_float4(f0.x, f0.y, f1.x, f1.y);
                } else {
                    xv = *(const float4*)((const float*)xin +
                                          (size_t)node * FIN + kc + 4 * c4);
                }
            }
            sX[(4 * c4 + 0) * BN + nn] = xv.x;
            sX[(4 * c4 + 1) * BN + nn] = xv.y;
            sX[(4 * c4 + 2) * BN + nn] = xv.z;
            sX[(4 * c4 + 3) * BN + nn] = xv.w;
        }
        __syncthreads();

#pragma unroll 8
        for (int k = 0; k < KC; k++) {
            float4 w = *(const float4*)(sW + k * FOUT + 4 * ot);
            unsigned long long w0 = pack2(w.x);
            unsigned long long w1 = pack2(w.y);
            unsigned long long w2 = pack2(w.z);
            unsigned long long w3 = pack2(w.w);
            const ulonglong2* xp = (const ulonglong2*)(sX + k * BN + n0);
#pragma unroll
            for (int q2 = 0; q2 < NP / 2; q2++) {
                ulonglong2 xv = xp[q2];
                acc[2 * q2][0] = fma2(xv.x, w0, acc[2 * q2][0]);
                acc[2 * q2][1] = fma2(xv.x, w1, acc[2 * q2][1]);
                acc[2 * q2][2] = fma2(xv.x, w2, acc[2 * q2][2]);
                acc[2 * q2][3] = fma2(xv.x, w3, acc[2 * q2][3]);
                acc[2 * q2 + 1][0] = fma2(xv.y, w0, acc[2 * q2 + 1][0]);
                acc[2 * q2 + 1][1] = fma2(xv.y, w1, acc[2 * q2 + 1][1]);
                acc[2 * q2 + 1][2] = fma2(xv.y, w2, acc[2 * q2 + 1][2]);
                acc[2 * q2 + 1][3] = fma2(xv.y, w3, acc[2 * q2 + 1][3]);
            }
        }
    }

    float4 bv = *(const float4*)(b + 4 * ot);
#pragma unroll
    for (int q = 0; q < NP; q++) {
        float2 o0 = unpack2(acc[q][0]);
        float2 o1 = unpack2(acc[q][1]);
        float2 o2 = unpack2(acc[q][2]);
        float2 o3 = unpack2(acc[q][3]);
        int na = nbase + n0 + 2 * q;
        float4 va = make_float4(o0.x + bv.x, o1.x + bv.y, o2.x + bv.z, o3.x + bv.w);
        float4 vb = make_float4(o0.y + bv.x, o1.y + bv.y, o2.y + bv.z, o3.y + bv.w);
        if (blockIdx.y == 0) {
            if (na < n) {
                __half2* yp = (__half2*)(y0h + (size_t)na * FOUT + 4 * ot);
                yp[0] = __floats2half2_rn(va.x, va.y);
                yp[1] = __floats2half2_rn(va.z, va.w);
            }
            if (na + 1 < n) {
                __half2* yp = (__half2*)(y0h + (size_t)(na + 1) * FOUT + 4 * ot);
                yp[0] = __floats2half2_rn(vb.x, vb.y);
                yp[1] = __floats2half2_rn(vb.z, vb.w);
            }
        } else {
            if (na < n)
                *(float4*)(y1f + (size_t)na * FOUT + 4 * ot) = va;
            if (na + 1 < n)
                *(float4*)(y1f + (size_t)(na + 1) * FOUT + 4 * ot) = vb;
        }
    }
}

// ---------------- fused GATv2 edge phase (fp16 gathers) ----------------
template <int U, int V, int G>
__device__ __forceinline__ void gat_block(const __half* __restrict__ xlh,
                                          const int* sidx, int cbase,
                                          const float (&xrv)[V],
                                          const float (&attv)[V],
                                          float (&acc)[V], float& z) {
    float a[U][V];
#pragma unroll
    for (int u = 0; u < U; u++) {
        const __half* p = xlh + (size_t)sidx[u] * (32 * V) + cbase;
        if constexpr (V == 4) {
            uint2 raw = *(const uint2*)p;
            float2 f0 = __half22float2(*reinterpret_cast<__half2*>(&raw.x));
            float2 f1 = __half22float2(*reinterpret_cast<__half2*>(&raw.y));
            a[u][0] = f0.x; a[u][1] = f0.y; a[u][2] = f1.x; a[u][3] = f1.y;
        } else {
            unsigned raw = *(const unsigned*)p;
            float2 f0 = __half22float2(*reinterpret_cast<__half2*>(&raw));
            a[u][0] = f0.x; a[u][1] = f0.y;
        }
    }
    float part[U];
#pragma unroll
    for (int u = 0; u < U; u++) {
        float pp = 0.f;
#pragma unroll
        for (int j = 0; j < V; j++) {
            float s = a[u][j] + xrv[j];
            s = (s > 0.f) ? s : 0.2f * s;
            pp += s * attv[j];
        }
        part[u] = pp;
    }
#pragma unroll
    for (int off = G / 2; off > 0; off >>= 1) {
#pragma unroll
        for (int u = 0; u < U; u++)
            part[u] += __shfl_xor_sync(0xffffffffu, part[u], off);
    }
    float p[U];
#pragma unroll
    for (int u = 0; u < U; u++) p[u] = __expf(part[u]);
#pragma unroll
    for (int u = 0; u < U; u++) z += p[u];
#pragma unroll
    for (int j = 0; j < V; j++) {
        float s = 0.f;
#pragma unroll
        for (int u = 0; u < U; u++) s += p[u] * a[u][j];
        acc[j] += s;
    }
}

// OUTH: write the output as fp16 (feeds the next layer's linear)
template <int H, int C, bool ELU, bool OUTH>
__global__ void gat_kernel(const __half* __restrict__ xlh,
                           const float* __restrict__ xr,
                           const float* __restrict__ att,
                           const float* __restrict__ bias,
                           void* __restrict__ out, int n) {
    constexpr int F = H * C;
    constexpr int V = F / 32;
    constexpr int G = 32 / H;

    int wid = (blockIdx.x * blockDim.x + threadIdx.x) >> 5;
    int lane = threadIdx.x & 31;
    if (wid >= n) return;
    int i = wid;
    int cbase = lane * V;

    float xrv[V], attv[V], acc[V];
    {
        const float* xp = xr + (size_t)i * F + cbase;
        if constexpr (V == 4) {
            float4 t = *(const float4*)xp;
            xrv[0] = t.x; xrv[1] = t.y; xrv[2] = t.z; xrv[3] = t.w;
        } else {
            float2 t = *(const float2*)xp;
            xrv[0] = t.x; xrv[1] = t.y;
        }
    }
#pragma unroll
    for (int j = 0; j < V; j++) { attv[j] = att[cbase + j]; acc[j] = 0.f; }

    float z = 0.f;
    int beg = g_rowptr[i], end = g_rowptr[i + 1];
    int k = beg;

    for (; k + 8 <= end; k += 8) {
        int s[8];
#pragma unroll
        for (int u = 0; u < 8; u++) s[u] = __ldg(g_srcs + k + u);
        gat_block<8, V, G>(xlh, s, cbase, xrv, attv, acc, z);
    }
    if (k + 4 <= end) {
        int s[4];
#pragma unroll
        for (int u = 0; u < 4; u++) s[u] = __ldg(g_srcs + k + u);
        gat_block<4, V, G>(xlh, s, cbase, xrv, attv, acc, z);
        k += 4;
    }
    for (; k < end; k++) {
        int s[1] = {__ldg(g_srcs + k)};
        gat_block<1, V, G>(xlh, s, cbase, xrv, attv, acc, z);
    }

    float inv = 1.f / (z + 1e-16f);
    float ov[V];
#pragma unroll
    for (int j = 0; j < V; j++) {
        float v = acc[j] * inv + bias[cbase + j];
        if constexpr (ELU) v = (v > 0.f) ? v : (__expf(v) - 1.f);
        ov[j] = v;
    }
    if constexpr (OUTH) {
        __half2* op = (__half2*)((__half*)out + (size_t)i * F + cbase);
        op[0] = __floats2half2_rn(ov[0], ov[1]);
        if constexpr (V == 4) op[1] = __floats2half2_rn(ov[2], ov[3]);
    } else {
        float* op = (float*)out + (size_t)i * F + cbase;
        if constexpr (V == 4)
            *(float4*)op = make_float4(ov[0], ov[1], ov[2], ov[3]);
        else
            *(float2*)op = make_float2(ov[0], ov[1]);
    }
}

// ---------------- launch ----------------

extern "C" void kernel_launch(void* const* d_in, const int* in_sizes, int n_in,
                              void* d_out, int out_size) {
    const float* x    = (const float*)d_in[0];
    const int*   ei   = (const int*)d_in[1];
    const float* Wl1  = (const float*)d_in[2];
    const float* bl1  = (const float*)d_in[3];
    const float* Wr1  = (const float*)d_in[4];
    const float* br1  = (const float*)d_in[5];
    const float* att1 = (const float*)d_in[6];
    const float* bias1= (const float*)d_in[7];
    const float* Wl2  = (const float*)d_in[8];
    const float* bl2  = (const float*)d_in[9];
    const float* Wr2  = (const float*)d_in[10];
    const float* br2  = (const float*)d_in[11];
    const float* att2 = (const float*)d_in[12];
    const float* bias2= (const float*)d_in[13];
    float* out = (float*)d_out;

    int n = in_sizes[0] / 64;   // 50000
    int e = in_sizes[1] / 2;    // 850000
    const int* src = ei;
    const int* dst = ei + e;
    int e4 = 0;
    if ((((unsigned long long)(size_t)src) & 15ull) == 0 &&
        (((unsigned long long)(size_t)dst) & 15ull) == 0) e4 = e / 4;

    __half *xlhp, *hhp;
    float *xrp, *wtp;
    cudaGetSymbolAddress((void**)&xlhp, g_xlh);
    cudaGetSymbolAddress((void**)&hhp,  g_hh);
    cudaGetSymbolAddress((void**)&xrp, g_xr);
    cudaGetSymbolAddress((void**)&wtp, g_wt);

    static cudaStream_t s_side = nullptr;
    static cudaEvent_t ev_fork = nullptr, ev_join = nullptr;
    if (s_side == nullptr) {
        cudaStreamCreateWithFlags(&s_side, cudaStreamNonBlocking);
        cudaEventCreateWithFlags(&ev_fork, cudaEventDisableTiming);
        cudaEventCreateWithFlags(&ev_join, cudaEventDisableTiming);
    }

    // fork: CSR build on side stream, concurrent with wt + linear1 on main.
    cudaEventRecord(ev_fork, 0);
    cudaStreamWaitEvent(s_side, ev_fork, 0);

    count_kernel<<<(max(e4, 1) + 255) / 256, 256, 0, s_side>>>(
        (const int4*)dst, e4, dst, e);
    scan_kernel<<<1, 1024, 0, s_side>>>(n);
    scatter_kernel<<<(max(e4, 1) + 255) / 256, 256, 0, s_side>>>(
        (const int4*)src, (const int4*)dst, e4, src, dst, e);
    cudaEventRecord(ev_join, s_side);

    // main stream: weight transpose + layer-1 linears
    wt_kernel<<<128, 256>>>(Wl1, Wr1, Wl2, Wr2);
    dim3 lgrid((n + 63) / 64, 2);
    linear2_kernel<64, 128, false><<<lgrid, 256>>>(
        x, wtp, bl1, xlhp, wtp + 8192, br1, xrp, n);

    // join: gat1 needs CSR + linear1
    cudaStreamWaitEvent(0, ev_join, 0);

    gat_kernel<4, 32, true, true><<<(n + 7) / 8, 256>>>(
        xlhp, xrp, att1, bias1, hhp, n);

    linear2_kernel<128, 64, true><<<lgrid, 256>>>(
        hhp, wtp + 16384, bl2, xlhp, wtp + 24576, br2, xrp, n);

    gat_kernel<1, 64, false, false><<<(n + 7) / 8, 256>>>(
        xlhp, xrp, att2, bias2, out, n);
}

// round 13
// speedup vs baseline: 1.1812x; 1.0090x over previous
#include <cuda_runtime.h>
#include <cuda_fp16.h>
#include <math.h>
#include <stdint.h>

#define NN 50000
#define EE 850000

// -------- device scratch (no allocations allowed) --------
// g_deg is zero at module load and re-zeroed by scan_kernel every call.
__device__ int g_deg[NN];
__device__ int g_cursor[NN];
__device__ int g_rowptr[NN + 1];
__device__ int g_srcs[EE];
__device__ __half g_xlh[(size_t)NN * 128];  // fp16 xl operand (both layers)
__device__ float g_xr[(size_t)NN * 128];    // fp32 xr operand (both layers)
__device__ __half g_hh[(size_t)NN * 128];   // layer-1 output (fp16)
__device__ float g_wt[4 * 8192];            // transposed weights

// ---------------- f32x2 packed math helpers ----------------
__device__ __forceinline__ unsigned long long pack2(float x) {
    unsigned long long r;
    asm("mov.b64 %0, {%1, %1};" : "=l"(r) : "f"(x));
    return r;
}
__device__ __forceinline__ unsigned long long fma2(unsigned long long a,
                                                   unsigned long long b,
                                                   unsigned long long c) {
    unsigned long long d;
    asm("fma.rn.f32x2 %0, %1, %2, %3;" : "=l"(d) : "l"(a), "l"(b), "l"(c));
    return d;
}
__device__ __forceinline__ float2 unpack2(unsigned long long v) {
    float2 r;
    asm("mov.b64 {%0, %1}, %2;" : "=f"(r.x), "=f"(r.y) : "l"(v));
    return r;
}

// ---------------- CSR build (4 edges/thread) ----------------

__global__ void count_kernel(const int4* __restrict__ dst4, int e4,
                             const int* __restrict__ dst, int e) {
    int i = blockIdx.x * blockDim.x + threadIdx.x;
    if (i < e4) {
        int4 d = dst4[i];
        atomicAdd(&g_deg[d.x], 1);
        atomicAdd(&g_deg[d.y], 1);
        atomicAdd(&g_deg[d.z], 1);
        atomicAdd(&g_deg[d.w], 1);
    }
    if (i == 0) {
        for (int k = 4 * e4; k < e; k++) atomicAdd(&g_deg[dst[k]], 1);
    }
}

// single-block exclusive scan; chunk=52 keeps ranges 4-aligned (int4 I/O).
// Re-zeros g_deg during the prefix pass so no memset launch is needed.
__global__ void scan_kernel(int n) {
    __shared__ int sdata[1024];
    int t = threadIdx.x;
    const int ch = 52;
    int s0 = t * ch;
    int s1 = min(s0 + ch, n);
    int sum = 0;
    if (s0 < n) {
        int i = s0;
        for (; i + 4 <= s1; i += 4) {
            int4 d = *(const int4*)(g_deg + i);
            sum += d.x + d.y + d.z + d.w;
        }
        for (; i < s1; i++) sum += g_deg[i];
    }
    sdata[t] = sum;
    __syncthreads();
    for (int off = 1; off < 1024; off <<= 1) {
        int v = (t >= off) ? sdata[t - off] : 0;
        __syncthreads();
        sdata[t] += v;
        __syncthreads();
    }
    int run = sdata[t] - sum;
    if (s0 < n) {
        const int4 zero4 = make_int4(0, 0, 0, 0);
        int i = s0;
        for (; i + 4 <= s1; i += 4) {
            int4 d = *(const int4*)(g_deg + i);
            int4 r;
            r.x = run;
            r.y = r.x + d.x;
            r.z = r.y + d.y;
            r.w = r.z + d.z;
            run = r.w + d.w;
            *(int4*)(g_rowptr + i) = r;
            *(int4*)(g_cursor + i) = r;
            *(int4*)(g_deg + i) = zero4;
        }
        for (; i < s1; i++) {
            g_rowptr[i] = run;
            g_cursor[i] = run;
            run += g_deg[i];
            g_deg[i] = 0;
        }
    }
    if (t == 1023) g_rowptr[n] = run;
}

__global__ void scatter_kernel(const int4* __restrict__ src4,
                               const int4* __restrict__ dst4, int e4,
                               const int* __restrict__ src,
                               const int* __restrict__ dst, int e) {
    int i = blockIdx.x * blockDim.x + threadIdx.x;
    if (i < e4) {
        int4 s = src4[i];
        int4 d = dst4[i];
        g_srcs[atomicAdd(&g_cursor[d.x], 1)] = s.x;
        g_srcs[atomicAdd(&g_cursor[d.y], 1)] = s.y;
        g_srcs[atomicAdd(&g_cursor[d.z], 1)] = s.z;
        g_srcs[atomicAdd(&g_cursor[d.w], 1)] = s.w;
    }
    if (i == 0) {
        for (int k = 4 * e4; k < e; k++)
            g_srcs[atomicAdd(&g_cursor[dst[k]], 1)] = src[k];
    }
}

// ---------------- weight transpose (tiny) ----------------
__global__ void wt_kernel(const float* __restrict__ Wl1,
                          const float* __restrict__ Wr1,
                          const float* __restrict__ Wl2,
                          const float* __restrict__ Wr2) {
    int idx = blockIdx.x * blockDim.x + threadIdx.x;   // 0 .. 32767
    int m = idx >> 13;
    int r = idx & 8191;
    const float* W = (m == 0) ? Wl1 : (m == 1) ? Wr1 : (m == 2) ? Wl2 : Wr2;
    int fin = (m < 2) ? 64 : 128;
    int fout = (m < 2) ? 128 : 64;
    int k = r / fout;
    int o = r - k * fout;
    g_wt[idx] = W[o * fin + k];   // Wt[k][o] = W[o][k]
}

// ---------------- smem dual linear ----------------
// INH: input x is fp16 (converted during sX staging).
// branch 0: y = x@Wl^T+bl -> fp16 (xl operand); branch 1: fp32 (xr operand)
template <int FIN, int FOUT, bool INH>
__global__ void __launch_bounds__(256)
linear2_kernel(const void* __restrict__ xin,
               const float* __restrict__ Wt0,
               const float* __restrict__ b0,
               __half* __restrict__ y0h,
               const float* __restrict__ Wt1,
               const float* __restrict__ b1,
               float* __restrict__ y1f,
               int n) {
    constexpr int BN = 64;
    constexpr int KC = 32;
    constexpr int OT = FOUT / 4;
    constexpr int NT = 256 / OT;
    constexpr int NPT = BN / NT;
    constexpr int NP = NPT / 2;

    __shared__ float sW[KC * FOUT];
    __shared__ float sX[KC * BN];

    const float* Wt = blockIdx.y ? Wt1 : Wt0;
    const float* b = blockIdx.y ? b1 : b0;

    int tid = threadIdx.x;
    int ot = tid % OT;
    int nt = tid / OT;
    int nbase = blockIdx.x * BN;
    int n0 = nt * NPT;

    unsigned long long acc[NP][4];
#pragma unroll
    for (int q = 0; q < NP; q++)
#pragma unroll
        for (int j = 0; j < 4; j++) acc[q][j] = 0ull;

    for (int kc = 0; kc < FIN; kc += KC) {
        __syncthreads();
        {
            const float4* wsrc = (const float4*)(Wt + (size_t)kc * FOUT);
#pragma unroll
            for (int idx = tid; idx < KC * FOUT / 4; idx += 256)
                ((float4*)sW)[idx] = wsrc[idx];
        }
#pragma unroll
        for (int idx = tid; idx < (KC / 4) * BN; idx += 256) {
            int nn = idx % BN;
            int c4 = idx / BN;
            int node = nbase + nn;
            float4 xv = make_float4(0.f, 0.f, 0.f, 0.f);
            if (node < n) {
                if constexpr (INH) {
                    uint2 raw = *(const uint2*)((const __half*)xin +
                                                (size_t)node * FIN + kc + 4 * c4);
                    float2 f0 = __half22float2(*reinterpret_cast<__half2*>(&raw.x));
                    float2 f1 = __half22float2(*reinterpret_cast<__half2*>(&raw.y));
                    xv = make_float4(f0.x, f0.y, f1.x, f1.y);
                } else {
                    xv = *(const float4*)((const float*)xin +
                                          (size_t)node * FIN + kc + 4 * c4);
                }
            }
            sX[(4 * c4 + 0) * BN + nn] = xv.x;
            sX[(4 * c4 + 1) * BN + nn] = xv.y;
            sX[(4 * c4 + 2) * BN + nn] = xv.z;
            sX[(4 * c4 + 3) * BN + nn] = xv.w;
        }
        __syncthreads();

#pragma unroll 8
        for (int k = 0; k < KC; k++) {
            float4 w = *(const float4*)(sW + k * FOUT + 4 * ot);
            unsigned long long w0 = pack2(w.x);
            unsigned long long w1 = pack2(w.y);
            unsigned long long w2 = pack2(w.z);
            unsigned long long w3 = pack2(w.w);
            const ulonglong2* xp = (const ulonglong2*)(sX + k * BN + n0);
#pragma unroll
            for (int q2 = 0; q2 < NP / 2; q2++) {
                ulonglong2 xv = xp[q2];
                acc[2 * q2][0] = fma2(xv.x, w0, acc[2 * q2][0]);
                acc[2 * q2][1] = fma2(xv.x, w1, acc[2 * q2][1]);
                acc[2 * q2][2] = fma2(xv.x, w2, acc[2 * q2][2]);
                acc[2 * q2][3] = fma2(xv.x, w3, acc[2 * q2][3]);
                acc[2 * q2 + 1][0] = fma2(xv.y, w0, acc[2 * q2 + 1][0]);
                acc[2 * q2 + 1][1] = fma2(xv.y, w1, acc[2 * q2 + 1][1]);
                acc[2 * q2 + 1][2] = fma2(xv.y, w2, acc[2 * q2 + 1][2]);
                acc[2 * q2 + 1][3] = fma2(xv.y, w3, acc[2 * q2 + 1][3]);
            }
        }
    }

    float4 bv = *(const float4*)(b + 4 * ot);
#pragma unroll
    for (int q = 0; q < NP; q++) {
        float2 o0 = unpack2(acc[q][0]);
        float2 o1 = unpack2(acc[q][1]);
        float2 o2 = unpack2(acc[q][2]);
        float2 o3 = unpack2(acc[q][3]);
        int na = nbase + n0 + 2 * q;
        float4 va = make_float4(o0.x + bv.x, o1.x + bv.y, o2.x + bv.z, o3.x + bv.w);
        float4 vb = make_float4(o0.y + bv.x, o1.y + bv.y, o2.y + bv.z, o3.y + bv.w);
        if (blockIdx.y == 0) {
            if (na < n) {
                __half2* yp = (__half2*)(y0h + (size_t)na * FOUT + 4 * ot);
                yp[0] = __floats2half2_rn(va.x, va.y);
                yp[1] = __floats2half2_rn(va.z, va.w);
            }
            if (na + 1 < n) {
                __half2* yp = (__half2*)(y0h + (size_t)(na + 1) * FOUT + 4 * ot);
                yp[0] = __floats2half2_rn(vb.x, vb.y);
                yp[1] = __floats2half2_rn(vb.z, vb.w);
            }
        } else {
            if (na < n)
                *(float4*)(y1f + (size_t)na * FOUT + 4 * ot) = va;
            if (na + 1 < n)
                *(float4*)(y1f + (size_t)(na + 1) * FOUT + 4 * ot) = vb;
        }
    }
}

// ---------------- fused GATv2 edge phase (fp16 gathers) ----------------
// V=4 floats per lane always (uint2 gathers). G = shfl reduce width.
// mask restricts the shfl to this node's lane group (half-warp for NW=2).
template <int U, int G>
__device__ __forceinline__ void gat_block(const __half* __restrict__ xlh,
                                          const int* sidx, int F, int cbase,
                                          unsigned mask,
                                          const float (&xrv)[4],
                                          const float (&attv)[4],
                                          float (&acc)[4], float& z) {
    float a[U][4];
#pragma unroll
    for (int u = 0; u < U; u++) {
        const __half* p = xlh + (size_t)sidx[u] * F + cbase;
        uint2 raw = *(const uint2*)p;
        float2 f0 = __half22float2(*reinterpret_cast<__half2*>(&raw.x));
        float2 f1 = __half22float2(*reinterpret_cast<__half2*>(&raw.y));
        a[u][0] = f0.x; a[u][1] = f0.y; a[u][2] = f1.x; a[u][3] = f1.y;
    }
    float part[U];
#pragma unroll
    for (int u = 0; u < U; u++) {
        float pp = 0.f;
#pragma unroll
        for (int j = 0; j < 4; j++) {
            float s = a[u][j] + xrv[j];
            s = (s > 0.f) ? s : 0.2f * s;
            pp += s * attv[j];
        }
        part[u] = pp;
    }
#pragma unroll
    for (int off = G / 2; off > 0; off >>= 1) {
#pragma unroll
        for (int u = 0; u < U; u++)
            part[u] += __shfl_xor_sync(mask, part[u], off);
    }
    float p[U];
#pragma unroll
    for (int u = 0; u < U; u++) p[u] = __expf(part[u]);
#pragma unroll
    for (int u = 0; u < U; u++) z += p[u];
#pragma unroll
    for (int j = 0; j < 4; j++) {
        float s = 0.f;
#pragma unroll
        for (int u = 0; u < U; u++) s += p[u] * a[u][j];
        acc[j] += s;
    }
}

// NW nodes per warp (L = 32/NW lanes per node, F = 4*L features).
// For NW=2 the halves run independent trip counts (divergent halves legal on
// Volta+; shfl masked to the half). No padding, no redundant gathers.
// G: shfl reduce width (= lanes per head). OUTH: fp16 output.
template <int F, int G, int NW, bool ELU, bool OUTH>
__global__ void gat_kernel(const __half* __restrict__ xlh,
                           const float* __restrict__ xr,
                           const float* __restrict__ att,
                           const float* __restrict__ bias,
                           void* __restrict__ out, int n) {
    constexpr int L = 32 / NW;
    static_assert(F == 4 * L, "V must be 4");

    int wid = (blockIdx.x * blockDim.x + threadIdx.x) >> 5;
    int lane = threadIdx.x & 31;
    int nw_needed = (n + NW - 1) / NW;
    if (wid >= nw_needed) return;

    int sub = lane / L;
    int l = lane & (L - 1);
    int node = wid * NW + sub;
    if (node >= n) return;   // only trailing half of last warp
    unsigned mask = (NW == 1) ? 0xffffffffu : (0xffffu << (sub * 16));
    int cbase = l * 4;

    float xrv[4], attv[4], acc[4] = {0.f, 0.f, 0.f, 0.f};
    {
        float4 t = *(const float4*)(xr + (size_t)node * F + cbase);
        xrv[0] = t.x; xrv[1] = t.y; xrv[2] = t.z; xrv[3] = t.w;
        float4 av = *(const float4*)(att + cbase);
        attv[0] = av.x; attv[1] = av.y; attv[2] = av.z; attv[3] = av.w;
    }

    float z = 0.f;
    int beg = g_rowptr[node], end = g_rowptr[node + 1];
    int k = beg;

    for (; k + 8 <= end; k += 8) {
        int s[8];
#pragma unroll
        for (int u = 0; u < 8; u++) s[u] = __ldg(g_srcs + k + u);
        gat_block<8, G>(xlh, s, F, cbase, mask, xrv, attv, acc, z);
    }
    if (k + 4 <= end) {
        int s[4];
#pragma unroll
        for (int u = 0; u < 4; u++) s[u] = __ldg(g_srcs + k + u);
        gat_block<4, G>(xlh, s, F, cbase, mask, xrv, attv, acc, z);
        k += 4;
    }
    for (; k < end; k++) {
        int s[1] = {__ldg(g_srcs + k)};
        gat_block<1, G>(xlh, s, F, cbase, mask, xrv, attv, acc, z);
    }

    float inv = 1.f / (z + 1e-16f);
    float ov[4];
#pragma unroll
    for (int j = 0; j < 4; j++) {
        float v = acc[j] * inv + bias[cbase + j];
        if constexpr (ELU) v = (v > 0.f) ? v : (__expf(v) - 1.f);
        ov[j] = v;
    }
    if constexpr (OUTH) {
        __half2* op = (__half2*)((__half*)out + (size_t)node * F + cbase);
        op[0] = __floats2half2_rn(ov[0], ov[1]);
        op[1] = __floats2half2_rn(ov[2], ov[3]);
    } else {
        *(float4*)((float*)out + (size_t)node * F + cbase) =
            make_float4(ov[0], ov[1], ov[2], ov[3]);
    }
}

// ---------------- launch ----------------

extern "C" void kernel_launch(void* const* d_in, const int* in_sizes, int n_in,
                              void* d_out, int out_size) {
    const float* x    = (const float*)d_in[0];
    const int*   ei   = (const int*)d_in[1];
    const float* Wl1  = (const float*)d_in[2];
    const float* bl1  = (const float*)d_in[3];
    const float* Wr1  = (const float*)d_in[4];
    const float* br1  = (const float*)d_in[5];
    const float* att1 = (const float*)d_in[6];
    const float* bias1= (const float*)d_in[7];
    const float* Wl2  = (const float*)d_in[8];
    const float* bl2  = (const float*)d_in[9];
    const float* Wr2  = (const float*)d_in[10];
    const float* br2  = (const float*)d_in[11];
    const float* att2 = (const float*)d_in[12];
    const float* bias2= (const float*)d_in[13];
    float* out = (float*)d_out;

    int n = in_sizes[0] / 64;   // 50000
    int e = in_sizes[1] / 2;    // 850000
    const int* src = ei;
    const int* dst = ei + e;
    int e4 = 0;
    if ((((unsigned long long)(size_t)src) & 15ull) == 0 &&
        (((unsigned long long)(size_t)dst) & 15ull) == 0) e4 = e / 4;

    __half *xlhp, *hhp;
    float *xrp, *wtp;
    cudaGetSymbolAddress((void**)&xlhp, g_xlh);
    cudaGetSymbolAddress((void**)&hhp,  g_hh);
    cudaGetSymbolAddress((void**)&xrp, g_xr);
    cudaGetSymbolAddress((void**)&wtp, g_wt);

    static cudaStream_t s_side = nullptr;
    static cudaEvent_t ev_fork = nullptr, ev_join = nullptr;
    if (s_side == nullptr) {
        cudaStreamCreateWithFlags(&s_side, cudaStreamNonBlocking);
        cudaEventCreateWithFlags(&ev_fork, cudaEventDisableTiming);
        cudaEventCreateWithFlags(&ev_join, cudaEventDisableTiming);
    }

    // fork: CSR build on side stream, concurrent with wt + linear1 on main.
    cudaEventRecord(ev_fork, 0);
    cudaStreamWaitEvent(s_side, ev_fork, 0);

    count_kernel<<<(max(e4, 1) + 255) / 256, 256, 0, s_side>>>(
        (const int4*)dst, e4, dst, e);
    scan_kernel<<<1, 1024, 0, s_side>>>(n);
    scatter_kernel<<<(max(e4, 1) + 255) / 256, 256, 0, s_side>>>(
        (const int4*)src, (const int4*)dst, e4, src, dst, e);
    cudaEventRecord(ev_join, s_side);

    // main stream: weight transpose + layer-1 linears
    wt_kernel<<<128, 256>>>(Wl1, Wr1, Wl2, Wr2);
    dim3 lgrid((n + 63) / 64, 2);
    linear2_kernel<64, 128, false><<<lgrid, 256>>>(
        x, wtp, bl1, xlhp, wtp + 8192, br1, xrp, n);

    // join: gat1 needs CSR + linear1
    cudaStreamWaitEvent(0, ev_join, 0);

    // gat1: 1 node/warp, F=128, heads of 8 lanes
    gat_kernel<128, 8, 1, true, true><<<(n + 7) / 8, 256>>>(
        xlhp, xrp, att1, bias1, hhp, n);

    linear2_kernel<128, 64, true><<<lgrid, 256>>>(
        hhp, wtp + 16384, bl2, xlhp, wtp + 24576, br2, xrp, n);

    // gat2: 2 nodes/warp (divergent halves), F=64, reduce over 16 lanes
    int w2 = (n + 1) / 2;
    gat_kernel<64, 16, 2, false, false><<<(w2 + 7) / 8, 256>>>(
        xlhp, xrp, att2, bias2, out, n);
}

// round 14
// speedup vs baseline: 1.2381x; 1.0481x over previous
#include <cuda_runtime.h>
#include <cuda_fp16.h>
#include <math.h>
#include <stdint.h>

#define NN 50000
#define EE 850000

// -------- device scratch (no allocations allowed) --------
// g_deg is zero at module load and re-zeroed by scan_kernel every call.
__device__ int g_deg[NN];
__device__ int g_cursor[NN];
__device__ int g_rowptr[NN + 1];
__device__ int g_srcs[EE];
__device__ __half g_xlh[(size_t)NN * 128];  // fp16 xl operand (both layers)
__device__ float g_xr[(size_t)NN * 128];    // fp32 xr operand (both layers)
__device__ __half g_hh[(size_t)NN * 128];   // layer-1 output (fp16)
__device__ float g_wt[4 * 8192];            // transposed weights

// ---------------- f32x2 packed math helpers ----------------
__device__ __forceinline__ unsigned long long pack2(float x) {
    unsigned long long r;
    asm("mov.b64 %0, {%1, %1};" : "=l"(r) : "f"(x));
    return r;
}
__device__ __forceinline__ unsigned long long fma2(unsigned long long a,
                                                   unsigned long long b,
                                                   unsigned long long c) {
    unsigned long long d;
    asm("fma.rn.f32x2 %0, %1, %2, %3;" : "=l"(d) : "l"(a), "l"(b), "l"(c));
    return d;
}
__device__ __forceinline__ float2 unpack2(unsigned long long v) {
    float2 r;
    asm("mov.b64 {%0, %1}, %2;" : "=f"(r.x), "=f"(r.y) : "l"(v));
    return r;
}

// ---------------- CSR build (4 edges/thread) ----------------

__global__ void count_kernel(const int4* __restrict__ dst4, int e4,
                             const int* __restrict__ dst, int e) {
    int i = blockIdx.x * blockDim.x + threadIdx.x;
    if (i < e4) {
        int4 d = dst4[i];
        atomicAdd(&g_deg[d.x], 1);
        atomicAdd(&g_deg[d.y], 1);
        atomicAdd(&g_deg[d.z], 1);
        atomicAdd(&g_deg[d.w], 1);
    }
    if (i == 0) {
        for (int k = 4 * e4; k < e; k++) atomicAdd(&g_deg[dst[k]], 1);
    }
}

// single-block exclusive scan; chunk=52 keeps ranges 4-aligned (int4 I/O).
// Re-zeros g_deg during the prefix pass so no memset launch is needed.
__global__ void scan_kernel(int n) {
    __shared__ int sdata[1024];
    int t = threadIdx.x;
    const int ch = 52;
    int s0 = t * ch;
    int s1 = min(s0 + ch, n);
    int sum = 0;
    if (s0 < n) {
        int i = s0;
        for (; i + 4 <= s1; i += 4) {
            int4 d = *(const int4*)(g_deg + i);
            sum += d.x + d.y + d.z + d.w;
        }
        for (; i < s1; i++) sum += g_deg[i];
    }
    sdata[t] = sum;
    __syncthreads();
    for (int off = 1; off < 1024; off <<= 1) {
        int v = (t >= off) ? sdata[t - off] : 0;
        __syncthreads();
        sdata[t] += v;
        __syncthreads();
    }
    int run = sdata[t] - sum;
    if (s0 < n) {
        const int4 zero4 = make_int4(0, 0, 0, 0);
        int i = s0;
        for (; i + 4 <= s1; i += 4) {
            int4 d = *(const int4*)(g_deg + i);
            int4 r;
            r.x = run;
            r.y = r.x + d.x;
            r.z = r.y + d.y;
            r.w = r.z + d.z;
            run = r.w + d.w;
            *(int4*)(g_rowptr + i) = r;
            *(int4*)(g_cursor + i) = r;
            *(int4*)(g_deg + i) = zero4;
        }
        for (; i < s1; i++) {
            g_rowptr[i] = run;
            g_cursor[i] = run;
            run += g_deg[i];
            g_deg[i] = 0;
        }
    }
    if (t == 1023) g_rowptr[n] = run;
}

__global__ void scatter_kernel(const int4* __restrict__ src4,
                               const int4* __restrict__ dst4, int e4,
                               const int* __restrict__ src,
                               const int* __restrict__ dst, int e) {
    int i = blockIdx.x * blockDim.x + threadIdx.x;
    if (i < e4) {
        int4 s = src4[i];
        int4 d = dst4[i];
        g_srcs[atomicAdd(&g_cursor[d.x], 1)] = s.x;
        g_srcs[atomicAdd(&g_cursor[d.y], 1)] = s.y;
        g_srcs[atomicAdd(&g_cursor[d.z], 1)] = s.z;
        g_srcs[atomicAdd(&g_cursor[d.w], 1)] = s.w;
    }
    if (i == 0) {
        for (int k = 4 * e4; k < e; k++)
            g_srcs[atomicAdd(&g_cursor[dst[k]], 1)] = src[k];
    }
}

// ---------------- weight transpose (tiny) ----------------
__global__ void wt_kernel(const float* __restrict__ Wl1,
                          const float* __restrict__ Wr1,
                          const float* __restrict__ Wl2,
                          const float* __restrict__ Wr2) {
    int idx = blockIdx.x * blockDim.x + threadIdx.x;   // 0 .. 32767
    int m = idx >> 13;
    int r = idx & 8191;
    const float* W = (m == 0) ? Wl1 : (m == 1) ? Wr1 : (m == 2) ? Wl2 : Wr2;
    int fin = (m < 2) ? 64 : 128;
    int fout = (m < 2) ? 128 : 64;
    int k = r / fout;
    int o = r - k * fout;
    g_wt[idx] = W[o * fin + k];   // Wt[k][o] = W[o][k]
}

// ---------------- smem dual linear ----------------
// Covers node range [nlo, nhi). INH: input x is fp16.
// branch 0: y = x@Wl^T+bl -> fp16 (xl operand); branch 1: fp32 (xr operand)
template <int FIN, int FOUT, bool INH>
__global__ void __launch_bounds__(256)
linear2_kernel(const void* __restrict__ xin,
               const float* __restrict__ Wt0,
               const float* __restrict__ b0,
               __half* __restrict__ y0h,
               const float* __restrict__ Wt1,
               const float* __restrict__ b1,
               float* __restrict__ y1f,
               int nlo, int nhi) {
    constexpr int BN = 64;
    constexpr int KC = 32;
    constexpr int OT = FOUT / 4;
    constexpr int NT = 256 / OT;
    constexpr int NPT = BN / NT;
    constexpr int NP = NPT / 2;

    __shared__ float sW[KC * FOUT];
    __shared__ float sX[KC * BN];

    const float* Wt = blockIdx.y ? Wt1 : Wt0;
    const float* b = blockIdx.y ? b1 : b0;

    int tid = threadIdx.x;
    int ot = tid % OT;
    int nt = tid / OT;
    int nbase = nlo + blockIdx.x * BN;
    int n0 = nt * NPT;

    unsigned long long acc[NP][4];
#pragma unroll
    for (int q = 0; q < NP; q++)
#pragma unroll
        for (int j = 0; j < 4; j++) acc[q][j] = 0ull;

    for (int kc = 0; kc < FIN; kc += KC) {
        __syncthreads();
        {
            const float4* wsrc = (const float4*)(Wt + (size_t)kc * FOUT);
#pragma unroll
            for (int idx = tid; idx < KC * FOUT / 4; idx += 256)
                ((float4*)sW)[idx] = wsrc[idx];
        }
#pragma unroll
        for (int idx = tid; idx < (KC / 4) * BN; idx += 256) {
            int nn = idx % BN;
            int c4 = idx / BN;
            int node = nbase + nn;
            float4 xv = make_float4(0.f, 0.f, 0.f, 0.f);
            if (node < nhi) {
                if constexpr (INH) {
                    uint2 raw = *(const uint2*)((const __half*)xin +
                                                (size_t)node * FIN + kc + 4 * c4);
                    float2 f0 = __half22float2(*reinterpret_cast<__half2*>(&raw.x));
                    float2 f1 = __half22float2(*reinterpret_cast<__half2*>(&raw.y));
                    xv = make_float4(f0.x, f0.y, f1.x, f1.y);
                } else {
                    xv = *(const float4*)((const float*)xin +
                                          (size_t)node * FIN + kc + 4 * c4);
                }
            }
            sX[(4 * c4 + 0) * BN + nn] = xv.x;
            sX[(4 * c4 + 1) * BN + nn] = xv.y;
            sX[(4 * c4 + 2) * BN + nn] = xv.z;
            sX[(4 * c4 + 3) * BN + nn] = xv.w;
        }
        __syncthreads();

#pragma unroll 8
        for (int k = 0; k < KC; k++) {
            float4 w = *(const float4*)(sW + k * FOUT + 4 * ot);
            unsigned long long w0 = pack2(w.x);
            unsigned long long w1 = pack2(w.y);
            unsigned long long w2 = pack2(w.z);
            unsigned long long w3 = pack2(w.w);
            const ulonglong2* xp = (const ulonglong2*)(sX + k * BN + n0);
#pragma unroll
            for (int q2 = 0; q2 < NP / 2; q2++) {
                ulonglong2 xv = xp[q2];
                acc[2 * q2][0] = fma2(xv.x, w0, acc[2 * q2][0]);
                acc[2 * q2][1] = fma2(xv.x, w1, acc[2 * q2][1]);
                acc[2 * q2][2] = fma2(xv.x, w2, acc[2 * q2][2]);
                acc[2 * q2][3] = fma2(xv.x, w3, acc[2 * q2][3]);
                acc[2 * q2 + 1][0] = fma2(xv.y, w0, acc[2 * q2 + 1][0]);
                acc[2 * q2 + 1][1] = fma2(xv.y, w1, acc[2 * q2 + 1][1]);
                acc[2 * q2 + 1][2] = fma2(xv.y, w2, acc[2 * q2 + 1][2]);
                acc[2 * q2 + 1][3] = fma2(xv.y, w3, acc[2 * q2 + 1][3]);
            }
        }
    }

    float4 bv = *(const float4*)(b + 4 * ot);
#pragma unroll
    for (int q = 0; q < NP; q++) {
        float2 o0 = unpack2(acc[q][0]);
        float2 o1 = unpack2(acc[q][1]);
        float2 o2 = unpack2(acc[q][2]);
        float2 o3 = unpack2(acc[q][3]);
        int na = nbase + n0 + 2 * q;
        float4 va = make_float4(o0.x + bv.x, o1.x + bv.y, o2.x + bv.z, o3.x + bv.w);
        float4 vb = make_float4(o0.y + bv.x, o1.y + bv.y, o2.y + bv.z, o3.y + bv.w);
        if (blockIdx.y == 0) {
            if (na < nhi) {
                __half2* yp = (__half2*)(y0h + (size_t)na * FOUT + 4 * ot);
                yp[0] = __floats2half2_rn(va.x, va.y);
                yp[1] = __floats2half2_rn(va.z, va.w);
            }
            if (na + 1 < nhi) {
                __half2* yp = (__half2*)(y0h + (size_t)(na + 1) * FOUT + 4 * ot);
                yp[0] = __floats2half2_rn(vb.x, vb.y);
                yp[1] = __floats2half2_rn(vb.z, vb.w);
            }
        } else {
            if (na < nhi)
                *(float4*)(y1f + (size_t)na * FOUT + 4 * ot) = va;
            if (na + 1 < nhi)
                *(float4*)(y1f + (size_t)(na + 1) * FOUT + 4 * ot) = vb;
        }
    }
}

// ---------------- fused GATv2 edge phase (fp16 gathers) ----------------
template <int U, int G>
__device__ __forceinline__ void gat_block(const __half* __restrict__ xlh,
                                          const int* sidx, int F, int cbase,
                                          unsigned mask,
                                          const float (&xrv)[4],
                                          const float (&attv)[4],
                                          float (&acc)[4], float& z) {
    float a[U][4];
#pragma unroll
    for (int u = 0; u < U; u++) {
        const __half* p = xlh + (size_t)sidx[u] * F + cbase;
        uint2 raw = *(const uint2*)p;
        float2 f0 = __half22float2(*reinterpret_cast<__half2*>(&raw.x));
        float2 f1 = __half22float2(*reinterpret_cast<__half2*>(&raw.y));
        a[u][0] = f0.x; a[u][1] = f0.y; a[u][2] = f1.x; a[u][3] = f1.y;
    }
    float part[U];
#pragma unroll
    for (int u = 0; u < U; u++) {
        float pp = 0.f;
#pragma unroll
        for (int j = 0; j < 4; j++) {
            float s = a[u][j] + xrv[j];
            s = (s > 0.f) ? s : 0.2f * s;
            pp += s * attv[j];
        }
        part[u] = pp;
    }
#pragma unroll
    for (int off = G / 2; off > 0; off >>= 1) {
#pragma unroll
        for (int u = 0; u < U; u++)
            part[u] += __shfl_xor_sync(mask, part[u], off);
    }
    float p[U];
#pragma unroll
    for (int u = 0; u < U; u++) p[u] = __expf(part[u]);
#pragma unroll
    for (int u = 0; u < U; u++) z += p[u];
#pragma unroll
    for (int j = 0; j < 4; j++) {
        float s = 0.f;
#pragma unroll
        for (int u = 0; u < U; u++) s += p[u] * a[u][j];
        acc[j] += s;
    }
}

// NW nodes per warp; covers node range [nlo, nhi). 128-thread blocks to
// reduce CTA-retire skew from degree variance.
template <int F, int G, int NW, bool ELU, bool OUTH>
__global__ void __launch_bounds__(128)
gat_kernel(const __half* __restrict__ xlh,
           const float* __restrict__ xr,
           const float* __restrict__ att,
           const float* __restrict__ bias,
           void* __restrict__ out, int nlo, int nhi) {
    constexpr int L = 32 / NW;
    static_assert(F == 4 * L, "V must be 4");

    int wid = (blockIdx.x * blockDim.x + threadIdx.x) >> 5;
    int lane = threadIdx.x & 31;
    int cnt = nhi - nlo;
    int nw_needed = (cnt + NW - 1) / NW;
    if (wid >= nw_needed) return;

    int sub = lane / L;
    int l = lane & (L - 1);
    int node = nlo + wid * NW + sub;
    if (node >= nhi) return;
    unsigned mask = (NW == 1) ? 0xffffffffu : (0xffffu << (sub * 16));
    int cbase = l * 4;

    float xrv[4], attv[4], acc[4] = {0.f, 0.f, 0.f, 0.f};
    {
        float4 t = *(const float4*)(xr + (size_t)node * F + cbase);
        xrv[0] = t.x; xrv[1] = t.y; xrv[2] = t.z; xrv[3] = t.w;
        float4 av = *(const float4*)(att + cbase);
        attv[0] = av.x; attv[1] = av.y; attv[2] = av.z; attv[3] = av.w;
    }

    float z = 0.f;
    int beg = g_rowptr[node], end = g_rowptr[node + 1];
    int k = beg;

    for (; k + 8 <= end; k += 8) {
        int s[8];
#pragma unroll
        for (int u = 0; u < 8; u++) s[u] = __ldg(g_srcs + k + u);
        gat_block<8, G>(xlh, s, F, cbase, mask, xrv, attv, acc, z);
    }
    if (k + 4 <= end) {
        int s[4];
#pragma unroll
        for (int u = 0; u < 4; u++) s[u] = __ldg(g_srcs + k + u);
        gat_block<4, G>(xlh, s, F, cbase, mask, xrv, attv, acc, z);
        k += 4;
    }
    for (; k < end; k++) {
        int s[1] = {__ldg(g_srcs + k)};
        gat_block<1, G>(xlh, s, F, cbase, mask, xrv, attv, acc, z);
    }

    float inv = 1.f / (z + 1e-16f);
    float ov[4];
#pragma unroll
    for (int j = 0; j < 4; j++) {
        float v = acc[j] * inv + bias[cbase + j];
        if constexpr (ELU) v = (v > 0.f) ? v : (__expf(v) - 1.f);
        ov[j] = v;
    }
    if constexpr (OUTH) {
        __half2* op = (__half2*)((__half*)out + (size_t)node * F + cbase);
        op[0] = __floats2half2_rn(ov[0], ov[1]);
        op[1] = __floats2half2_rn(ov[2], ov[3]);
    } else {
        *(float4*)((float*)out + (size_t)node * F + cbase) =
            make_float4(ov[0], ov[1], ov[2], ov[3]);
    }
}

// ---------------- launch ----------------

extern "C" void kernel_launch(void* const* d_in, const int* in_sizes, int n_in,
                              void* d_out, int out_size) {
    const float* x    = (const float*)d_in[0];
    const int*   ei   = (const int*)d_in[1];
    const float* Wl1  = (const float*)d_in[2];
    const float* bl1  = (const float*)d_in[3];
    const float* Wr1  = (const float*)d_in[4];
    const float* br1  = (const float*)d_in[5];
    const float* att1 = (const float*)d_in[6];
    const float* bias1= (const float*)d_in[7];
    const float* Wl2  = (const float*)d_in[8];
    const float* bl2  = (const float*)d_in[9];
    const float* Wr2  = (const float*)d_in[10];
    const float* br2  = (const float*)d_in[11];
    const float* att2 = (const float*)d_in[12];
    const float* bias2= (const float*)d_in[13];
    float* out = (float*)d_out;

    int n = in_sizes[0] / 64;   // 50000
    int e = in_sizes[1] / 2;    // 850000
    const int* src = ei;
    const int* dst = ei + e;
    int e4 = 0;
    if ((((unsigned long long)(size_t)src) & 15ull) == 0 &&
        (((unsigned long long)(size_t)dst) & 15ull) == 0) e4 = e / 4;

    __half *xlhp, *hhp;
    float *xrp, *wtp;
    cudaGetSymbolAddress((void**)&xlhp, g_xlh);
    cudaGetSymbolAddress((void**)&hhp,  g_hh);
    cudaGetSymbolAddress((void**)&xrp, g_xr);
    cudaGetSymbolAddress((void**)&wtp, g_wt);

    static cudaStream_t s_side = nullptr;
    static cudaEvent_t ev_fork = nullptr, ev_join = nullptr;
    static cudaEvent_t ev_g1a = nullptr, ev_l2a = nullptr;
    if (s_side == nullptr) {
        cudaStreamCreateWithFlags(&s_side, cudaStreamNonBlocking);
        cudaEventCreateWithFlags(&ev_fork, cudaEventDisableTiming);
        cudaEventCreateWithFlags(&ev_join, cudaEventDisableTiming);
        cudaEventCreateWithFlags(&ev_g1a, cudaEventDisableTiming);
        cudaEventCreateWithFlags(&ev_l2a, cudaEventDisableTiming);
    }

    // fork: CSR build on side stream, concurrent with wt + linear1 on main.
    cudaEventRecord(ev_fork, 0);
    cudaStreamWaitEvent(s_side, ev_fork, 0);

    count_kernel<<<(max(e4, 1) + 255) / 256, 256, 0, s_side>>>(
        (const int4*)dst, e4, dst, e);
    scan_kernel<<<1, 1024, 0, s_side>>>(n);
    scatter_kernel<<<(max(e4, 1) + 255) / 256, 256, 0, s_side>>>(
        (const int4*)src, (const int4*)dst, e4, src, dst, e);
    cudaEventRecord(ev_join, s_side);

    // main stream: weight transpose + layer-1 linears
    wt_kernel<<<128, 256>>>(Wl1, Wr1, Wl2, Wr2);
    dim3 lgrid1((n + 63) / 64, 2);
    linear2_kernel<64, 128, false><<<lgrid1, 256>>>(
        x, wtp, bl1, xlhp, wtp + 8192, br1, xrp, 0, n);

    // join: gat1 needs CSR + linear1
    cudaStreamWaitEvent(0, ev_join, 0);

    // --- chunked gat1 / linear2 overlap ---
    int half = ((n / 2) + 63) & ~63;   // 64-aligned split for linear tiles

    // gat1 first half (main)
    gat_kernel<128, 8, 1, true, true><<<(half + 3) / 4, 128>>>(
        xlhp, xrp, att1, bias1, hhp, 0, half);
    cudaEventRecord(ev_g1a, 0);

    // gat1 second half (main) runs concurrently with linear2 first half (side)
    gat_kernel<128, 8, 1, true, true><<<((n - half) + 3) / 4, 128>>>(
        xlhp, xrp, att1, bias1, hhp, half, n);

    cudaStreamWaitEvent(s_side, ev_g1a, 0);
    dim3 lgrid2a((half + 63) / 64, 2);
    linear2_kernel<128, 64, true><<<lgrid2a, 256, 0, s_side>>>(
        hhp, wtp + 16384, bl2, xlhp, wtp + 24576, br2, xrp, 0, half);
    cudaEventRecord(ev_l2a, s_side);

    // linear2 second half (main, after gat1_b by program order)
    dim3 lgrid2b((n - half + 63) / 64, 2);
    linear2_kernel<128, 64, true><<<lgrid2b, 256>>>(
        hhp, wtp + 16384, bl2, xlhp, wtp + 24576, br2, xrp, half, n);

    // gat2 needs both linear2 halves
    cudaStreamWaitEvent(0, ev_l2a, 0);
    int w2 = (n + 1) / 2;
    gat_kernel<64, 16, 2, false, false><<<(w2 + 3) / 4, 128>>>(
        xlhp, xrp, att2, bias2, out, 0, n);
}